// round 15
// baseline (speedup 1.0000x reference)
#include <cuda_runtime.h>
#include <cuda_fp16.h>
#include <math.h>
#include <stdint.h>

#define BB 64
#define LL 256
#define HH 1024
#define EE 1024
#define VV 50257
#define H3 3072

// ================= scratch (__device__ globals) =============================
__device__ __align__(16) __half g_xhi[BB * 1024];
__device__ __align__(16) __half g_xlo[BB * 1024];
__device__ __align__(16) __half g_hhi[BB * 1024];
__device__ __align__(16) __half g_hlo[BB * 1024];
__device__ __align__(16) __half g_cat_hi[BB * 2 * HH];
__device__ __align__(16) __half g_cat_lo[BB * 2 * HH];
__device__ float g_gi[BB * H3];                // atomic-accumulated
__device__ float g_gh[BB * H3];                // atomic-accumulated
__device__ float g_hb[BB];
__device__ float g_q[BB * HH];                 // atomic-accumulated
__device__ float g_scores[BB * LL];
__device__ float g_cp[BB * HH];                // atomic-accumulated (concat)
__device__ __align__(16) float g_ctxp[BB * 4 * HH];   // online-softmax partials
__device__ float2 g_msp[BB * 4];               // (max, sum) per partial

// ================= helpers ===================================================
__device__ __forceinline__ uint32_t smem_u32(const void* p) {
    uint32_t a;
    asm("{ .reg .u64 t; cvta.to.shared.u64 t, %1; cvt.u32.u64 %0, t; }"
        : "=r"(a) : "l"(p));
    return a;
}

__device__ __forceinline__ void ldsm_x4(uint32_t addr, uint32_t& d0, uint32_t& d1,
                                        uint32_t& d2, uint32_t& d3) {
    asm volatile("ldmatrix.sync.aligned.m8n8.x4.shared.b16 {%0,%1,%2,%3}, [%4];"
                 : "=r"(d0), "=r"(d1), "=r"(d2), "=r"(d3) : "r"(addr));
}

__device__ __forceinline__ void mma_f16(float* c, uint32_t a0, uint32_t a1,
                                        uint32_t a2, uint32_t a3,
                                        uint32_t b0, uint32_t b1) {
    asm volatile(
        "mma.sync.aligned.m16n8k16.row.col.f32.f16.f16.f32 "
        "{%0,%1,%2,%3}, {%4,%5,%6,%7}, {%8,%9}, {%0,%1,%2,%3};"
        : "+f"(c[0]), "+f"(c[1]), "+f"(c[2]), "+f"(c[3])
        : "r"(a0), "r"(a1), "r"(a2), "r"(a3), "r"(b0), "r"(b1));
}

__device__ __forceinline__ uint32_t pack_h(float a, float b) {
    __half2 t = __floats2half2_rn(a, b);
    return *reinterpret_cast<uint32_t*>(&t);
}

// ================= double-buffered fused-convert HMMA GEMM (fp16) ===========
// C[64, n] = sum_k fp32(A[64,k]) * W[n,k] (+bias), fp16 hi/lo compensated.
// NP=3: Ahi*Whi + Ahi*Wlo + Alo*Whi (err ~2^-22) — pre-softmax math, occ 2.
// NP=1: Ahi*Whi (err ~2^-11.5) — post-softmax GEMMs (concat, logits), occ 3.
// ATANH=1 (NP=1 only): A staged as fp16(tanhf(ath[row,k] + athb[k]))
//   — folds the concat epilogue into the logits GEMM's A path.
// CTA 64x128, 8 warps 4x2 of 16x64. W fp32 read once.
// wtrans=0: W[n,k] stride K; wtrans=1: W[k,n] stride ldw.
// atomic=1: atomicAdd into pre-zeroed C (no bias); else direct write (+bias).
#define STR 40

template <int NP, int ATANH>
__global__ __launch_bounds__(256, (NP == 1 ? 3 : 2))
void hmma_gemm(const __half* __restrict__ Ahi0, const __half* __restrict__ Alo0,
               const float* __restrict__ W0, float* __restrict__ C0,
               const __half* __restrict__ Ahi1, const __half* __restrict__ Alo1,
               const float* __restrict__ W1, float* __restrict__ C1,
               const float* __restrict__ bias, int Ntot, int K, int ldc,
               int lda, int ldw, int wtrans, int atomic,
               const float* __restrict__ ath, const float* __restrict__ athb) {
    extern __shared__ __half sm[];

    constexpr bool HAS_ALO = (NP >= 3);
    constexpr bool HAS_WLO = (NP >= 2);
    constexpr int OFF_ALO_ = 64 * STR;
    constexpr int OFF_WHI_ = OFF_ALO_ + (HAS_ALO ? 64 * STR : 0);
    constexpr int OFF_WLO_ = OFF_WHI_ + 128 * STR;
    constexpr int STG_ELEMS = OFF_WLO_ + (HAS_WLO ? 128 * STR : 0);
    constexpr int STG_BYTES = STG_ELEMS * 2;

    const __half* Ahi = blockIdx.y ? Ahi1 : Ahi0;
    const __half* Alo = blockIdx.y ? Alo1 : Alo0;
    const float* W = blockIdx.y ? W1 : W0;
    float* C = blockIdx.y ? C1 : C0;

    const int tid = threadIdx.x, wid = tid >> 5, lane = tid & 31;
    const int wr = wid & 3, wc = wid >> 2;
    const int n0 = blockIdx.x * 128;

    const int kper = K / gridDim.z;
    const int koff = blockIdx.z * kper;
    const int nchunks = kper >> 5;

    const int r = tid >> 1, hf = tid & 1;
    const bool wv = (n0 + r) < Ntot;
    const float* wrow = W + (size_t)(n0 + r) * K + koff + hf * 16;
    const float* wtb  = W + (size_t)(koff + hf * 16) * ldw + (n0 + r);
    const __half* arow_hi = Ahi + (size_t)(r & 63) * lda + koff + hf * 16;
    const __half* arow_lo = Alo + (size_t)(r & 63) * lda + koff + hf * 16;
    const float* atrow = ATANH ? (ath + (size_t)(r & 63) * lda + koff + hf * 16)
                               : nullptr;
    const float* atb   = ATANH ? (athb + koff + hf * 16) : nullptr;
    const bool do_a = (tid < 128);

    const int am = lane >> 3, aln = lane & 7;
    const int arow2 = wr * 16 + aln + (am & 1) * 8;
    const int akoff = (am >> 1) * 8;
    const uint32_t aHiB = smem_u32(&sm[arow2 * STR + akoff]);
    const uint32_t aLoB = smem_u32(&sm[OFF_ALO_ + arow2 * STR + akoff]);
    const int brow_base = wc * 64 + aln + (am >> 1) * 8;
    const int bkoff = (am & 1) * 8;
    const uint32_t bHiB = smem_u32(&sm[OFF_WHI_ + brow_base * STR + bkoff]);
    const uint32_t bLoB = smem_u32(&sm[OFF_WLO_ + brow_base * STR + bkoff]);

    float acc[8][4];
#pragma unroll
    for (int i = 0; i < 8; i++)
#pragma unroll
        for (int j = 0; j < 4; j++) acc[i][j] = 0.f;

    float wreg[HAS_WLO ? 16 : 1];
    uint32_t wregh[HAS_WLO ? 1 : 8];
    uint4 ahreg[2], alreg[2];

    auto load_chunk = [&](int ck) {
        if (wv) {
            if (!wtrans) {
                const float4* p = (const float4*)(wrow + (size_t)ck * 32);
#pragma unroll
                for (int i = 0; i < 4; i++) {
                    float4 f = p[i];
                    if (HAS_WLO) {
                        wreg[i * 4 + 0] = f.x; wreg[i * 4 + 1] = f.y;
                        wreg[i * 4 + 2] = f.z; wreg[i * 4 + 3] = f.w;
                    } else {
                        wregh[i * 2 + 0] = pack_h(f.x, f.y);
                        wregh[i * 2 + 1] = pack_h(f.z, f.w);
                    }
                }
            } else {
                const float* p = wtb + (size_t)ck * 32 * ldw;
                if (HAS_WLO) {
#pragma unroll
                    for (int i = 0; i < 16; i++) wreg[i] = p[(size_t)i * ldw];
                } else {
#pragma unroll
                    for (int i = 0; i < 8; i++)
                        wregh[i] = pack_h(p[(size_t)(2 * i) * ldw],
                                          p[(size_t)(2 * i + 1) * ldw]);
                }
            }
        }
        if (do_a) {
            if (ATANH) {
                const float4* ap = (const float4*)(atrow + (size_t)ck * 32);
                const float4* bp = (const float4*)(atb + (size_t)ck * 32);
#pragma unroll
                for (int j = 0; j < 2; j++) {
                    float4 a0 = ap[j * 2 + 0];
                    float4 b0 = bp[j * 2 + 0];
                    float t0 = tanhf(a0.x + b0.x), t1 = tanhf(a0.y + b0.y);
                    float t2 = tanhf(a0.z + b0.z), t3 = tanhf(a0.w + b0.w);
                    float4 a1 = ap[j * 2 + 1];
                    float4 b1 = bp[j * 2 + 1];
                    float t4 = tanhf(a1.x + b1.x), t5 = tanhf(a1.y + b1.y);
                    float t6 = tanhf(a1.z + b1.z), t7 = tanhf(a1.w + b1.w);
                    ahreg[j] = make_uint4(pack_h(t0, t1), pack_h(t2, t3),
                                          pack_h(t4, t5), pack_h(t6, t7));
                }
            } else {
                const uint4* ph = (const uint4*)(arow_hi + (size_t)ck * 32);
                ahreg[0] = ph[0]; ahreg[1] = ph[1];
                if (HAS_ALO) {
                    const uint4* pl = (const uint4*)(arow_lo + (size_t)ck * 32);
                    alreg[0] = pl[0]; alreg[1] = pl[1];
                }
            }
        }
    };

    auto store_stage = [&](int st) {
        const int so = st * STG_ELEMS;
        int wb = so + OFF_WHI_ + r * STR + hf * 16;
        if (HAS_WLO) {
            int wb2 = so + OFF_WLO_ + r * STR + hf * 16;
#pragma unroll
            for (int qq = 0; qq < 2; qq++) {
                uint4 hv;
                float f0 = wreg[qq * 8 + 0], f1 = wreg[qq * 8 + 1];
                float f2 = wreg[qq * 8 + 2], f3 = wreg[qq * 8 + 3];
                float f4 = wreg[qq * 8 + 4], f5 = wreg[qq * 8 + 5];
                float f6 = wreg[qq * 8 + 6], f7 = wreg[qq * 8 + 7];
                hv.x = pack_h(f0, f1); hv.y = pack_h(f2, f3);
                hv.z = pack_h(f4, f5); hv.w = pack_h(f6, f7);
                *(uint4*)&sm[wb + qq * 8] = hv;
                uint4 lv;
                float h0 = __half2float(__float2half_rn(f0));
                float h1 = __half2float(__float2half_rn(f1));
                float h2 = __half2float(__float2half_rn(f2));
                float h3 = __half2float(__float2half_rn(f3));
                float h4 = __half2float(__float2half_rn(f4));
                float h5 = __half2float(__float2half_rn(f5));
                float h6 = __half2float(__float2half_rn(f6));
                float h7 = __half2float(__float2half_rn(f7));
                lv.x = pack_h(f0 - h0, f1 - h1);
                lv.y = pack_h(f2 - h2, f3 - h3);
                lv.z = pack_h(f4 - h4, f5 - h5);
                lv.w = pack_h(f6 - h6, f7 - h7);
                *(uint4*)&sm[wb2 + qq * 8] = lv;
            }
        } else {
            *(uint4*)&sm[wb + 0] = make_uint4(wregh[0], wregh[1], wregh[2], wregh[3]);
            *(uint4*)&sm[wb + 8] = make_uint4(wregh[4], wregh[5], wregh[6], wregh[7]);
        }
        if (do_a) {
            int ab = so + r * STR + hf * 16;
            *(uint4*)&sm[ab + 0] = ahreg[0];
            *(uint4*)&sm[ab + 8] = ahreg[1];
            if (HAS_ALO) {
                int ab2 = so + OFF_ALO_ + r * STR + hf * 16;
                *(uint4*)&sm[ab2 + 0] = alreg[0];
                *(uint4*)&sm[ab2 + 8] = alreg[1];
            }
        }
    };

    if (!wv) {
        if (HAS_WLO) {
#pragma unroll
            for (int i = 0; i < 16; i++) wreg[i] = 0.f;
        } else {
#pragma unroll
            for (int i = 0; i < 8; i++) wregh[i] = 0u;
        }
    }

    load_chunk(0);
    store_stage(0);
    __syncthreads();

    for (int ck = 0; ck < nchunks; ck++) {
        const bool more = (ck + 1 < nchunks);
        if (more) load_chunk(ck + 1);

        const uint32_t so = (uint32_t)(ck & 1) * STG_BYTES;
#pragma unroll
        for (int ks = 0; ks < 2; ks++) {
            uint32_t ah0, ah1, ah2, ah3;
            uint32_t al0, al1, al2, al3;
            ldsm_x4(aHiB + so + ks * 32, ah0, ah1, ah2, ah3);
            if (HAS_ALO) ldsm_x4(aLoB + so + ks * 32, al0, al1, al2, al3);
#pragma unroll
            for (int nf = 0; nf < 4; nf++) {
                const uint32_t off = so + nf * (16 * STR * 2) + ks * 32;
                uint32_t bh0, bh1, bh2, bh3;
                ldsm_x4(bHiB + off, bh0, bh1, bh2, bh3);
                mma_f16(acc[nf * 2],     ah0, ah1, ah2, ah3, bh0, bh1);
                mma_f16(acc[nf * 2 + 1], ah0, ah1, ah2, ah3, bh2, bh3);
                if (HAS_WLO) {
                    uint32_t bl0, bl1, bl2, bl3;
                    ldsm_x4(bLoB + off, bl0, bl1, bl2, bl3);
                    mma_f16(acc[nf * 2],     ah0, ah1, ah2, ah3, bl0, bl1);
                    mma_f16(acc[nf * 2 + 1], ah0, ah1, ah2, ah3, bl2, bl3);
                }
                if (HAS_ALO) {
                    mma_f16(acc[nf * 2],     al0, al1, al2, al3, bh0, bh1);
                    mma_f16(acc[nf * 2 + 1], al0, al1, al2, al3, bh2, bh3);
                }
            }
        }

        if (more) store_stage((ck + 1) & 1);
        __syncthreads();
    }

    const int qrow = lane >> 2, qcol = (lane & 3) * 2;
    const int m0 = wr * 16 + qrow;
    if (atomic) {
#pragma unroll
        for (int nf = 0; nf < 8; nf++) {
            int n = n0 + wc * 64 + nf * 8 + qcol;
            if (n < Ntot) {
                atomicAdd(&C[(size_t)m0 * ldc + n], acc[nf][0]);
                atomicAdd(&C[(size_t)(m0 + 8) * ldc + n], acc[nf][2]);
            }
            if (n + 1 < Ntot) {
                atomicAdd(&C[(size_t)m0 * ldc + n + 1], acc[nf][1]);
                atomicAdd(&C[(size_t)(m0 + 8) * ldc + n + 1], acc[nf][3]);
            }
        }
    } else {
        const bool use_bias = (bias != nullptr);
#pragma unroll
        for (int nf = 0; nf < 8; nf++) {
            int n = n0 + wc * 64 + nf * 8 + qcol;
            float b0v = 0.f, b1v = 0.f;
            if (use_bias) {
                if (n < Ntot) b0v = bias[n];
                if (n + 1 < Ntot) b1v = bias[n + 1];
            }
            if (n < Ntot) {
                C[(size_t)m0 * ldc + n] = acc[nf][0] + b0v;
                C[(size_t)(m0 + 8) * ldc + n] = acc[nf][2] + b0v;
            }
            if (n + 1 < Ntot) {
                C[(size_t)m0 * ldc + n + 1] = acc[nf][1] + b1v;
                C[(size_t)(m0 + 8) * ldc + n + 1] = acc[nf][3] + b1v;
            }
        }
    }
}

#define SMEM_NP3 ((64 * STR + 64 * STR + 128 * STR + 128 * STR) * 2 * 2)
#define SMEM_NP1 ((64 * STR + 128 * STR) * 2 * 2)

// ======= fused hi/lo split prep (emb gather + h0) + accumulator zeroing ======
__global__ void split_all(const int* __restrict__ seq, const float* __restrict__ emb,
                          const float* __restrict__ h0,
                          __half* __restrict__ xhi, __half* __restrict__ xlo,
                          __half* __restrict__ hhi, __half* __restrict__ hlo,
                          float* __restrict__ q, float* __restrict__ cp,
                          float* __restrict__ hb,
                          float* __restrict__ gi, float* __restrict__ gh) {
    int r = blockIdx.x, t = threadIdx.x;
    const float* src;
    __half *hi, *lo;
    int row;
    if (r < BB) {
        src = emb + (size_t)seq[r] * EE; hi = xhi; lo = xlo; row = r;
    } else {
        row = r - BB;
        src = h0 + (size_t)row * HH; hi = hhi; lo = hlo;
    }
    float4 f = ((const float4*)src)[t];
    float h0v = __half2float(__float2half_rn(f.x));
    float h1v = __half2float(__float2half_rn(f.y));
    float h2v = __half2float(__float2half_rn(f.z));
    float h3v = __half2float(__float2half_rn(f.w));
    uint2 hv = make_uint2(pack_h(f.x, f.y), pack_h(f.z, f.w));
    uint2 lv = make_uint2(pack_h(f.x - h0v, f.y - h1v),
                          pack_h(f.z - h2v, f.w - h3v));
    *(uint2*)(hi + (size_t)row * 1024 + t * 4) = hv;
    *(uint2*)(lo + (size_t)row * 1024 + t * 4) = lv;

    // zero the atomic accumulators
    int g = r * 256 + t;                 // 0..32767
    float2 z2 = make_float2(0.f, 0.f);
    ((float2*)q)[g] = z2;
    ((float2*)cp)[g] = z2;
#pragma unroll
    for (int u = 0; u < 3; u++) {
        ((float2*)gi)[g + u * 32768] = z2;
        ((float2*)gh)[g + u * 32768] = z2;
    }
    if (g < BB) hb[g] = 0.f;
}

// ================= fused GRU combine + hb (grid 64x4, atomic hb) =============
__global__ void gru_combine_hb(const float* __restrict__ gi,
                               const float* __restrict__ gh,
                               const float* __restrict__ b_ih,
                               const float* __restrict__ b_hh,
                               const float* __restrict__ hprev,
                               const float* __restrict__ attn_b,
                               __half* __restrict__ cat_hi,
                               __half* __restrict__ cat_lo,
                               float* __restrict__ out_hidden,
                               float* __restrict__ hb) {
    int b = blockIdx.x, t = threadIdx.x;
    int j = blockIdx.y * 256 + t;
    size_t base = (size_t)b * H3 + j;
    float ir = gi[base] + b_ih[j];
    float iz = gi[base + HH] + b_ih[HH + j];
    float in_ = gi[base + 2 * HH] + b_ih[2 * HH + j];
    float hr = gh[base] + b_hh[j];
    float hz = gh[base + HH] + b_hh[HH + j];
    float hn = gh[base + 2 * HH] + b_hh[2 * HH + j];
    float r = 1.f / (1.f + expf(-(ir + hr)));
    float z = 1.f / (1.f + expf(-(iz + hz)));
    float n = tanhf(in_ + r * hn);
    float hp = hprev[(size_t)b * HH + j];
    float hnew = (1.f - z) * n + z * hp;
    out_hidden[(size_t)b * HH + j] = hnew;
    __half h = __float2half_rn(hnew);
    cat_hi[(size_t)b * 2048 + j] = h;
    cat_lo[(size_t)b * 2048 + j] = __float2half_rn(hnew - __half2float(h));
    float hb_acc = hnew * attn_b[j];
    __shared__ float smr[256];
    smr[t] = hb_acc;
    __syncthreads();
    for (int st = 128; st > 0; st >>= 1) {
        if (t < st) smr[t] += smr[t + st];
        __syncthreads();
    }
    if (t == 0) atomicAdd(&hb[b], smr[0]);
}

// ====== online-softmax attention, pass 1: scores + partial contexts ==========
// grid (64 b, 4 l-chunks) = 256 CTAs (single wave at occ 2).
// 8 warps; warp owns 8 l's. enc read exactly once.
__global__ __launch_bounds__(256)
void attn_part(const float* __restrict__ q, const float* __restrict__ enc,
               const float* __restrict__ hb, float* __restrict__ scores,
               float* __restrict__ ctxp, float2* __restrict__ msp) {
    const int b = blockIdx.x, chunk = blockIdx.y;
    const int tid = threadIdx.x, wid = tid >> 5, lane = tid & 31;
    __shared__ float swap[8 * 1024];
    __shared__ float sm_m[8], sm_s[8];

    float4 qv[8];
    const float4* qp = (const float4*)(q + (size_t)b * HH);
#pragma unroll
    for (int rp = 0; rp < 8; rp++) qv[rp] = qp[lane + rp * 32];

    float4 acc[8];
#pragma unroll
    for (int rp = 0; rp < 8; rp++) acc[rp] = make_float4(0.f, 0.f, 0.f, 0.f);
    float m = -INFINITY, ssum = 0.f;
    const float hbv = hb[b];
    const int l0 = chunk * 64 + wid * 8;

    for (int li = 0; li < 8; li++) {
        const int l = l0 + li;
        const float4* ep = (const float4*)(enc + ((size_t)l * BB + b) * HH);
        float4 ev[8];
        float dot = 0.f;
#pragma unroll
        for (int rp = 0; rp < 8; rp++) {
            ev[rp] = ep[lane + rp * 32];
            dot += ev[rp].x * qv[rp].x + ev[rp].y * qv[rp].y
                 + ev[rp].z * qv[rp].z + ev[rp].w * qv[rp].w;
        }
#pragma unroll
        for (int o = 16; o > 0; o >>= 1) dot += __shfl_xor_sync(0xffffffffu, dot, o);
        float s_l = dot + hbv;
        if (lane == 0) scores[(size_t)b * LL + l] = s_l;
        float m_new = fmaxf(m, s_l);
        float scale = expf(m - m_new);
        float p = expf(s_l - m_new);
        ssum = ssum * scale + p;
#pragma unroll
        for (int rp = 0; rp < 8; rp++) {
            acc[rp].x = acc[rp].x * scale + p * ev[rp].x;
            acc[rp].y = acc[rp].y * scale + p * ev[rp].y;
            acc[rp].z = acc[rp].z * scale + p * ev[rp].z;
            acc[rp].w = acc[rp].w * scale + p * ev[rp].w;
        }
        m = m_new;
    }

    // CTA combine (8 warp partials -> 1)
    float4* wp = (float4*)(swap + wid * 1024);
#pragma unroll
    for (int rp = 0; rp < 8; rp++) wp[lane + rp * 32] = acc[rp];
    if (lane == 0) { sm_m[wid] = m; sm_s[wid] = ssum; }
    __syncthreads();

    float mc = sm_m[0];
#pragma unroll
    for (int w2 = 1; w2 < 8; w2++) mc = fmaxf(mc, sm_m[w2]);
    float scl[8];
    float sc_sum = 0.f;
#pragma unroll
    for (int w2 = 0; w2 < 8; w2++) {
        scl[w2] = expf(sm_m[w2] - mc);
        sc_sum += scl[w2] * sm_s[w2];
    }
    float4 cx = make_float4(0.f, 0.f, 0.f, 0.f);
#pragma unroll
    for (int w2 = 0; w2 < 8; w2++) {
        float4 v = ((float4*)(swap + w2 * 1024))[tid];
        cx.x += scl[w2] * v.x; cx.y += scl[w2] * v.y;
        cx.z += scl[w2] * v.z; cx.w += scl[w2] * v.w;
    }
    ((float4*)(ctxp + ((size_t)b * 4 + chunk) * HH))[tid] = cx;
    if (tid == 0) msp[b * 4 + chunk] = make_float2(mc, sc_sum);
}

// ====== online-softmax attention, pass 2: merge partials + outputs ===========
__global__ void attn_reduce(const float* __restrict__ scores,
                            const float* __restrict__ ctxp,
                            const float2* __restrict__ msp,
                            float* __restrict__ out_attn,
                            __half* __restrict__ cat_hi,
                            __half* __restrict__ cat_lo) {
    const int b = blockIdx.x, t = threadIdx.x;  // 256 threads
    float2 ms[4];
#pragma unroll
    for (int c = 0; c < 4; c++) ms[c] = msp[b * 4 + c];
    float M = ms[0].x;
#pragma unroll
    for (int c = 1; c < 4; c++) M = fmaxf(M, ms[c].x);
    float S = 0.f;
    float scl[4];
#pragma unroll
    for (int c = 0; c < 4; c++) {
        scl[c] = expf(ms[c].x - M);
        S += scl[c] * ms[c].y;
    }
    float invS = 1.f / S;

    float4 cx = make_float4(0.f, 0.f, 0.f, 0.f);
#pragma unroll
    for (int c = 0; c < 4; c++) {
        float4 v = ((const float4*)(ctxp + ((size_t)b * 4 + c) * HH))[t];
        cx.x += scl[c] * v.x; cx.y += scl[c] * v.y;
        cx.z += scl[c] * v.z; cx.w += scl[c] * v.w;
    }
    cx.x *= invS; cx.y *= invS; cx.z *= invS; cx.w *= invS;

    size_t o = (size_t)b * 2048 + 1024 + t * 4;
    float hx = __half2float(__float2half_rn(cx.x));
    float hy = __half2float(__float2half_rn(cx.y));
    float hz = __half2float(__float2half_rn(cx.z));
    float hw = __half2float(__float2half_rn(cx.w));
    *(uint2*)(cat_hi + o) = make_uint2(pack_h(cx.x, cx.y), pack_h(cx.z, cx.w));
    *(uint2*)(cat_lo + o) = make_uint2(pack_h(cx.x - hx, cx.y - hy),
                                       pack_h(cx.z - hz, cx.w - hw));

    float w = expf(scores[(size_t)b * LL + t] - M) * invS;
    out_attn[(size_t)b * LL + t] = w;
}

// ================= launch =====================================================
extern "C" void kernel_launch(void* const* d_in, const int* in_sizes, int n_in,
                              void* d_out, int out_size) {
    const int*   seq  = (const int*)d_in[0];
    const float* h0   = (const float*)d_in[1];
    const float* enc  = (const float*)d_in[2];
    const float* emb  = (const float*)d_in[3];
    const float* w_ih = (const float*)d_in[4];
    const float* w_hh = (const float*)d_in[5];
    const float* b_ih = (const float*)d_in[6];
    const float* b_hh = (const float*)d_in[7];
    const float* attw = (const float*)d_in[8];
    const float* attb = (const float*)d_in[9];
    const float* cw   = (const float*)d_in[10];
    const float* cb   = (const float*)d_in[11];
    const float* ow   = (const float*)d_in[12];
    const float* ob   = (const float*)d_in[13];

    float* out        = (float*)d_out;                  // [B, V]
    float* out_hidden = out + (size_t)BB * VV;          // [B, H]
    float* out_attn   = out_hidden + (size_t)BB * HH;   // [B, L]

    cudaFuncSetAttribute(hmma_gemm<3, 0>,
                         cudaFuncAttributeMaxDynamicSharedMemorySize, SMEM_NP3);
    cudaFuncSetAttribute(hmma_gemm<1, 0>,
                         cudaFuncAttributeMaxDynamicSharedMemorySize, SMEM_NP1);
    cudaFuncSetAttribute(hmma_gemm<1, 1>,
                         cudaFuncAttributeMaxDynamicSharedMemorySize, SMEM_NP1);

    __half *xhi, *xlo, *hhi, *hlo, *cathi, *catlo;
    float *gi, *gh, *hb, *q, *sc, *cp, *ctxp;
    float2* msp;
    cudaGetSymbolAddress((void**)&xhi, g_xhi);
    cudaGetSymbolAddress((void**)&xlo, g_xlo);
    cudaGetSymbolAddress((void**)&hhi, g_hhi);
    cudaGetSymbolAddress((void**)&hlo, g_hlo);
    cudaGetSymbolAddress((void**)&cathi, g_cat_hi);
    cudaGetSymbolAddress((void**)&catlo, g_cat_lo);
    cudaGetSymbolAddress((void**)&gi, g_gi);
    cudaGetSymbolAddress((void**)&gh, g_gh);
    cudaGetSymbolAddress((void**)&hb, g_hb);
    cudaGetSymbolAddress((void**)&q, g_q);
    cudaGetSymbolAddress((void**)&sc, g_scores);
    cudaGetSymbolAddress((void**)&cp, g_cp);
    cudaGetSymbolAddress((void**)&ctxp, g_ctxp);
    cudaGetSymbolAddress((void**)&msp, g_msp);

    // 1) fp16 hi/lo splits (emb gather + h0) + zero all atomic accumulators
    split_all<<<128, 256>>>(seq, emb, h0, xhi, xlo, hhi, hlo, q, cp, hb, gi, gh);

    // 2) GRU gate GEMMs (3-pass; split-K=8 -> 384 CTAs, atomic epilogue)
    hmma_gemm<3, 0><<<dim3(24, 2, 8), 256, SMEM_NP3>>>(
        xhi, xlo, w_ih, gi, hhi, hlo, w_hh, gh,
        nullptr, H3, EE, H3, EE, 0, 0, 1, nullptr, nullptr);

    // 3) gates -> h_new (hidden output, cat hi/lo first half, hb via atomics)
    gru_combine_hb<<<dim3(BB, 4), 256>>>(gi, gh, b_ih, b_hh, h0, attb,
                                         cathi, catlo, out_hidden, hb);

    // 4) q = h_new @ attn_w (3-pass, transposed W, split-K=16, atomic epilogue)
    hmma_gemm<3, 0><<<dim3(8, 1, 16), 256, SMEM_NP3>>>(
        cathi, catlo, attw, q, cathi, catlo, attw, q,
        nullptr, HH, HH, HH, 2048, HH, 1, 1, nullptr, nullptr);

    // 5) online-softmax attention: enc read once (256 CTAs = 1 wave) + merge
    attn_part<<<dim3(BB, 4), 256>>>(q, enc, hb, sc, ctxp, msp);
    attn_reduce<<<BB, 256>>>(sc, ctxp, msp, out_attn, cathi, catlo);

    // 6) concat GEMM (NP=1, split-K=16, atomic epilogue into cp)
    hmma_gemm<1, 0><<<dim3(8, 1, 16), 256, SMEM_NP1>>>(
        cathi, cathi, cw, cp, cathi, cathi, cw, cp,
        nullptr, HH, 2048, HH, 2048, 0, 0, 1, nullptr, nullptr);

    // 7) big V-GEMM: single-pass fp16, occ 3; A = tanh(cp + cb) fused in-kernel
    hmma_gemm<1, 1><<<dim3((VV + 127) / 128, 1, 1), 256, SMEM_NP1>>>(
        nullptr, nullptr, ow, out, nullptr, nullptr, ow, out,
        ob, VV, HH, VV, HH, 0, 0, 0, cp, cb);
}

// round 16
// speedup vs baseline: 1.1716x; 1.1716x over previous
#include <cuda_runtime.h>
#include <cuda_fp16.h>
#include <math.h>
#include <stdint.h>

#define BB 64
#define LL 256
#define HH 1024
#define EE 1024
#define VV 50257
#define H3 3072

// ================= scratch (__device__ globals) =============================
__device__ __align__(16) __half g_xhi[BB * 1024];
__device__ __align__(16) __half g_xlo[BB * 1024];
__device__ __align__(16) __half g_hhi[BB * 1024];
__device__ __align__(16) __half g_hlo[BB * 1024];
__device__ __align__(16) __half g_chi[BB * 1024];
__device__ __align__(16) __half g_cat_hi[BB * 2 * HH];
__device__ __align__(16) __half g_cat_lo[BB * 2 * HH];
__device__ float g_gi[BB * H3];                // atomic-accumulated
__device__ float g_gh[BB * H3];                // atomic-accumulated
__device__ float g_hb[BB];
__device__ float g_q[BB * HH];                 // atomic-accumulated
__device__ float g_scores[BB * LL];
__device__ float g_cp[BB * HH];                // atomic-accumulated (concat)
__device__ __align__(16) float g_ctxp[BB * 4 * HH];   // online-softmax partials
__device__ float2 g_msp[BB * 4];               // (max, sum) per partial

// ================= helpers ===================================================
__device__ __forceinline__ uint32_t smem_u32(const void* p) {
    uint32_t a;
    asm("{ .reg .u64 t; cvta.to.shared.u64 t, %1; cvt.u32.u64 %0, t; }"
        : "=r"(a) : "l"(p));
    return a;
}

__device__ __forceinline__ void ldsm_x4(uint32_t addr, uint32_t& d0, uint32_t& d1,
                                        uint32_t& d2, uint32_t& d3) {
    asm volatile("ldmatrix.sync.aligned.m8n8.x4.shared.b16 {%0,%1,%2,%3}, [%4];"
                 : "=r"(d0), "=r"(d1), "=r"(d2), "=r"(d3) : "r"(addr));
}

__device__ __forceinline__ void mma_f16(float* c, uint32_t a0, uint32_t a1,
                                        uint32_t a2, uint32_t a3,
                                        uint32_t b0, uint32_t b1) {
    asm volatile(
        "mma.sync.aligned.m16n8k16.row.col.f32.f16.f16.f32 "
        "{%0,%1,%2,%3}, {%4,%5,%6,%7}, {%8,%9}, {%0,%1,%2,%3};"
        : "+f"(c[0]), "+f"(c[1]), "+f"(c[2]), "+f"(c[3])
        : "r"(a0), "r"(a1), "r"(a2), "r"(a3), "r"(b0), "r"(b1));
}

__device__ __forceinline__ uint32_t pack_h(float a, float b) {
    __half2 t = __floats2half2_rn(a, b);
    return *reinterpret_cast<uint32_t*>(&t);
}

// ================= double-buffered fused-convert HMMA GEMM (fp16) ===========
// C[64, n] = sum_k fp32(A[64,k]) * W[n,k] (+bias), fp16 hi/lo compensated.
// NP=3: Ahi*Whi + Ahi*Wlo + Alo*Whi (err ~2^-22) — pre-softmax math, occ 2.
// NP=1: Ahi*Whi (err ~2^-11.5) — post-softmax GEMMs (concat, logits), occ 3.
// CTA 64x128, 8 warps 4x2 of 16x64. W fp32 read once.
// wtrans=0: W[n,k] stride K; wtrans=1: W[k,n] stride ldw.
// atomic=1: atomicAdd into pre-zeroed C (no bias); else direct write (+bias).
#define STR 40

template <int NP>
__global__ __launch_bounds__(256, (NP == 1 ? 3 : 2))
void hmma_gemm(const __half* __restrict__ Ahi0, const __half* __restrict__ Alo0,
               const float* __restrict__ W0, float* __restrict__ C0,
               const __half* __restrict__ Ahi1, const __half* __restrict__ Alo1,
               const float* __restrict__ W1, float* __restrict__ C1,
               const float* __restrict__ bias, int Ntot, int K, int ldc,
               int lda, int ldw, int wtrans, int atomic) {
    extern __shared__ __half sm[];

    constexpr bool HAS_ALO = (NP >= 3);
    constexpr bool HAS_WLO = (NP >= 2);
    constexpr int OFF_ALO_ = 64 * STR;
    constexpr int OFF_WHI_ = OFF_ALO_ + (HAS_ALO ? 64 * STR : 0);
    constexpr int OFF_WLO_ = OFF_WHI_ + 128 * STR;
    constexpr int STG_ELEMS = OFF_WLO_ + (HAS_WLO ? 128 * STR : 0);
    constexpr int STG_BYTES = STG_ELEMS * 2;

    const __half* Ahi = blockIdx.y ? Ahi1 : Ahi0;
    const __half* Alo = blockIdx.y ? Alo1 : Alo0;
    const float* W = blockIdx.y ? W1 : W0;
    float* C = blockIdx.y ? C1 : C0;

    const int tid = threadIdx.x, wid = tid >> 5, lane = tid & 31;
    const int wr = wid & 3, wc = wid >> 2;
    const int n0 = blockIdx.x * 128;

    const int kper = K / gridDim.z;
    const int koff = blockIdx.z * kper;
    const int nchunks = kper >> 5;

    const int r = tid >> 1, hf = tid & 1;
    const bool wv = (n0 + r) < Ntot;
    const float* wrow = W + (size_t)(n0 + r) * K + koff + hf * 16;
    const float* wtb  = W + (size_t)(koff + hf * 16) * ldw + (n0 + r);
    const __half* arow_hi = Ahi + (size_t)(r & 63) * lda + koff + hf * 16;
    const __half* arow_lo = Alo + (size_t)(r & 63) * lda + koff + hf * 16;
    const bool do_a = (tid < 128);

    const int am = lane >> 3, aln = lane & 7;
    const int arow2 = wr * 16 + aln + (am & 1) * 8;
    const int akoff = (am >> 1) * 8;
    const uint32_t aHiB = smem_u32(&sm[arow2 * STR + akoff]);
    const uint32_t aLoB = smem_u32(&sm[OFF_ALO_ + arow2 * STR + akoff]);
    const int brow_base = wc * 64 + aln + (am >> 1) * 8;
    const int bkoff = (am & 1) * 8;
    const uint32_t bHiB = smem_u32(&sm[OFF_WHI_ + brow_base * STR + bkoff]);
    const uint32_t bLoB = smem_u32(&sm[OFF_WLO_ + brow_base * STR + bkoff]);

    float acc[8][4];
#pragma unroll
    for (int i = 0; i < 8; i++)
#pragma unroll
        for (int j = 0; j < 4; j++) acc[i][j] = 0.f;

    float wreg[HAS_WLO ? 16 : 1];
    uint32_t wregh[HAS_WLO ? 1 : 8];
    uint4 ahreg[2], alreg[2];

    auto load_chunk = [&](int ck) {
        if (wv) {
            if (!wtrans) {
                const float4* p = (const float4*)(wrow + (size_t)ck * 32);
#pragma unroll
                for (int i = 0; i < 4; i++) {
                    float4 f = p[i];
                    if (HAS_WLO) {
                        wreg[i * 4 + 0] = f.x; wreg[i * 4 + 1] = f.y;
                        wreg[i * 4 + 2] = f.z; wreg[i * 4 + 3] = f.w;
                    } else {
                        wregh[i * 2 + 0] = pack_h(f.x, f.y);
                        wregh[i * 2 + 1] = pack_h(f.z, f.w);
                    }
                }
            } else {
                const float* p = wtb + (size_t)ck * 32 * ldw;
                if (HAS_WLO) {
#pragma unroll
                    for (int i = 0; i < 16; i++) wreg[i] = p[(size_t)i * ldw];
                } else {
#pragma unroll
                    for (int i = 0; i < 8; i++)
                        wregh[i] = pack_h(p[(size_t)(2 * i) * ldw],
                                          p[(size_t)(2 * i + 1) * ldw]);
                }
            }
        }
        if (do_a) {
            const uint4* ph = (const uint4*)(arow_hi + (size_t)ck * 32);
            ahreg[0] = ph[0]; ahreg[1] = ph[1];
            if (HAS_ALO) {
                const uint4* pl = (const uint4*)(arow_lo + (size_t)ck * 32);
                alreg[0] = pl[0]; alreg[1] = pl[1];
            }
        }
    };

    auto store_stage = [&](int st) {
        const int so = st * STG_ELEMS;
        int wb = so + OFF_WHI_ + r * STR + hf * 16;
        if (HAS_WLO) {
            int wb2 = so + OFF_WLO_ + r * STR + hf * 16;
#pragma unroll
            for (int qq = 0; qq < 2; qq++) {
                uint4 hv;
                float f0 = wreg[qq * 8 + 0], f1 = wreg[qq * 8 + 1];
                float f2 = wreg[qq * 8 + 2], f3 = wreg[qq * 8 + 3];
                float f4 = wreg[qq * 8 + 4], f5 = wreg[qq * 8 + 5];
                float f6 = wreg[qq * 8 + 6], f7 = wreg[qq * 8 + 7];
                hv.x = pack_h(f0, f1); hv.y = pack_h(f2, f3);
                hv.z = pack_h(f4, f5); hv.w = pack_h(f6, f7);
                *(uint4*)&sm[wb + qq * 8] = hv;
                uint4 lv;
                float h0 = __half2float(__float2half_rn(f0));
                float h1 = __half2float(__float2half_rn(f1));
                float h2 = __half2float(__float2half_rn(f2));
                float h3 = __half2float(__float2half_rn(f3));
                float h4 = __half2float(__float2half_rn(f4));
                float h5 = __half2float(__float2half_rn(f5));
                float h6 = __half2float(__float2half_rn(f6));
                float h7 = __half2float(__float2half_rn(f7));
                lv.x = pack_h(f0 - h0, f1 - h1);
                lv.y = pack_h(f2 - h2, f3 - h3);
                lv.z = pack_h(f4 - h4, f5 - h5);
                lv.w = pack_h(f6 - h6, f7 - h7);
                *(uint4*)&sm[wb2 + qq * 8] = lv;
            }
        } else {
            *(uint4*)&sm[wb + 0] = make_uint4(wregh[0], wregh[1], wregh[2], wregh[3]);
            *(uint4*)&sm[wb + 8] = make_uint4(wregh[4], wregh[5], wregh[6], wregh[7]);
        }
        if (do_a) {
            int ab = so + r * STR + hf * 16;
            *(uint4*)&sm[ab + 0] = ahreg[0];
            *(uint4*)&sm[ab + 8] = ahreg[1];
            if (HAS_ALO) {
                int ab2 = so + OFF_ALO_ + r * STR + hf * 16;
                *(uint4*)&sm[ab2 + 0] = alreg[0];
                *(uint4*)&sm[ab2 + 8] = alreg[1];
            }
        }
    };

    if (!wv) {
        if (HAS_WLO) {
#pragma unroll
            for (int i = 0; i < 16; i++) wreg[i] = 0.f;
        } else {
#pragma unroll
            for (int i = 0; i < 8; i++) wregh[i] = 0u;
        }
    }

    load_chunk(0);
    store_stage(0);
    __syncthreads();

    for (int ck = 0; ck < nchunks; ck++) {
        const bool more = (ck + 1 < nchunks);
        if (more) load_chunk(ck + 1);

        const uint32_t so = (uint32_t)(ck & 1) * STG_BYTES;
#pragma unroll
        for (int ks = 0; ks < 2; ks++) {
            uint32_t ah0, ah1, ah2, ah3;
            uint32_t al0, al1, al2, al3;
            ldsm_x4(aHiB + so + ks * 32, ah0, ah1, ah2, ah3);
            if (HAS_ALO) ldsm_x4(aLoB + so + ks * 32, al0, al1, al2, al3);
#pragma unroll
            for (int nf = 0; nf < 4; nf++) {
                const uint32_t off = so + nf * (16 * STR * 2) + ks * 32;
                uint32_t bh0, bh1, bh2, bh3;
                ldsm_x4(bHiB + off, bh0, bh1, bh2, bh3);
                mma_f16(acc[nf * 2],     ah0, ah1, ah2, ah3, bh0, bh1);
                mma_f16(acc[nf * 2 + 1], ah0, ah1, ah2, ah3, bh2, bh3);
                if (HAS_WLO) {
                    uint32_t bl0, bl1, bl2, bl3;
                    ldsm_x4(bLoB + off, bl0, bl1, bl2, bl3);
                    mma_f16(acc[nf * 2],     ah0, ah1, ah2, ah3, bl0, bl1);
                    mma_f16(acc[nf * 2 + 1], ah0, ah1, ah2, ah3, bl2, bl3);
                }
                if (HAS_ALO) {
                    mma_f16(acc[nf * 2],     al0, al1, al2, al3, bh0, bh1);
                    mma_f16(acc[nf * 2 + 1], al0, al1, al2, al3, bh2, bh3);
                }
            }
        }

        if (more) store_stage((ck + 1) & 1);
        __syncthreads();
    }

    const int qrow = lane >> 2, qcol = (lane & 3) * 2;
    const int m0 = wr * 16 + qrow;
    if (atomic) {
#pragma unroll
        for (int nf = 0; nf < 8; nf++) {
            int n = n0 + wc * 64 + nf * 8 + qcol;
            if (n < Ntot) {
                atomicAdd(&C[(size_t)m0 * ldc + n], acc[nf][0]);
                atomicAdd(&C[(size_t)(m0 + 8) * ldc + n], acc[nf][2]);
            }
            if (n + 1 < Ntot) {
                atomicAdd(&C[(size_t)m0 * ldc + n + 1], acc[nf][1]);
                atomicAdd(&C[(size_t)(m0 + 8) * ldc + n + 1], acc[nf][3]);
            }
        }
    } else {
        const bool use_bias = (bias != nullptr);
#pragma unroll
        for (int nf = 0; nf < 8; nf++) {
            int n = n0 + wc * 64 + nf * 8 + qcol;
            float b0v = 0.f, b1v = 0.f;
            if (use_bias) {
                if (n < Ntot) b0v = bias[n];
                if (n + 1 < Ntot) b1v = bias[n + 1];
            }
            if (n < Ntot) {
                C[(size_t)m0 * ldc + n] = acc[nf][0] + b0v;
                C[(size_t)(m0 + 8) * ldc + n] = acc[nf][2] + b0v;
            }
            if (n + 1 < Ntot) {
                C[(size_t)m0 * ldc + n + 1] = acc[nf][1] + b1v;
                C[(size_t)(m0 + 8) * ldc + n + 1] = acc[nf][3] + b1v;
            }
        }
    }
}

#define SMEM_NP3 ((64 * STR + 64 * STR + 128 * STR + 128 * STR) * 2 * 2)
#define SMEM_NP1 ((64 * STR + 128 * STR) * 2 * 2)

// ======= fused hi/lo split prep (emb gather + h0) + accumulator zeroing ======
__global__ void split_all(const int* __restrict__ seq, const float* __restrict__ emb,
                          const float* __restrict__ h0,
                          __half* __restrict__ xhi, __half* __restrict__ xlo,
                          __half* __restrict__ hhi, __half* __restrict__ hlo,
                          float* __restrict__ q, float* __restrict__ cp,
                          float* __restrict__ hb,
                          float* __restrict__ gi, float* __restrict__ gh) {
    int r = blockIdx.x, t = threadIdx.x;
    const float* src;
    __half *hi, *lo;
    int row;
    if (r < BB) {
        src = emb + (size_t)seq[r] * EE; hi = xhi; lo = xlo; row = r;
    } else {
        row = r - BB;
        src = h0 + (size_t)row * HH; hi = hhi; lo = hlo;
    }
    float4 f = ((const float4*)src)[t];
    float h0v = __half2float(__float2half_rn(f.x));
    float h1v = __half2float(__float2half_rn(f.y));
    float h2v = __half2float(__float2half_rn(f.z));
    float h3v = __half2float(__float2half_rn(f.w));
    uint2 hv = make_uint2(pack_h(f.x, f.y), pack_h(f.z, f.w));
    uint2 lv = make_uint2(pack_h(f.x - h0v, f.y - h1v),
                          pack_h(f.z - h2v, f.w - h3v));
    *(uint2*)(hi + (size_t)row * 1024 + t * 4) = hv;
    *(uint2*)(lo + (size_t)row * 1024 + t * 4) = lv;

    // zero the atomic accumulators
    int g = r * 256 + t;                 // 0..32767
    float2 z2 = make_float2(0.f, 0.f);
    ((float2*)q)[g] = z2;
    ((float2*)cp)[g] = z2;
#pragma unroll
    for (int u = 0; u < 3; u++) {
        ((float2*)gi)[g + u * 32768] = z2;
        ((float2*)gh)[g + u * 32768] = z2;
    }
    if (g < BB) hb[g] = 0.f;
}

// ========= reduce (single accumulated buffer) + bias + tanh + fp16 ===========
__global__ void reduce_tanh_split(const float* __restrict__ P,
                                  const float* __restrict__ bias,
                                  __half* __restrict__ hi) {
    int idx = blockIdx.x * blockDim.x + threadIdx.x;  // 65536
    float s = tanhf(P[idx] + bias[idx & 1023]);
    hi[idx] = __float2half_rn(s);
}

// ================= fused GRU combine + hb (grid 64x4, atomic hb) =============
__global__ void gru_combine_hb(const float* __restrict__ gi,
                               const float* __restrict__ gh,
                               const float* __restrict__ b_ih,
                               const float* __restrict__ b_hh,
                               const float* __restrict__ hprev,
                               const float* __restrict__ attn_b,
                               __half* __restrict__ cat_hi,
                               __half* __restrict__ cat_lo,
                               float* __restrict__ out_hidden,
                               float* __restrict__ hb) {
    int b = blockIdx.x, t = threadIdx.x;
    int j = blockIdx.y * 256 + t;
    size_t base = (size_t)b * H3 + j;
    float ir = gi[base] + b_ih[j];
    float iz = gi[base + HH] + b_ih[HH + j];
    float in_ = gi[base + 2 * HH] + b_ih[2 * HH + j];
    float hr = gh[base] + b_hh[j];
    float hz = gh[base + HH] + b_hh[HH + j];
    float hn = gh[base + 2 * HH] + b_hh[2 * HH + j];
    float r = 1.f / (1.f + expf(-(ir + hr)));
    float z = 1.f / (1.f + expf(-(iz + hz)));
    float n = tanhf(in_ + r * hn);
    float hp = hprev[(size_t)b * HH + j];
    float hnew = (1.f - z) * n + z * hp;
    out_hidden[(size_t)b * HH + j] = hnew;
    __half h = __float2half_rn(hnew);
    cat_hi[(size_t)b * 2048 + j] = h;
    cat_lo[(size_t)b * 2048 + j] = __float2half_rn(hnew - __half2float(h));
    float hb_acc = hnew * attn_b[j];
    __shared__ float smr[256];
    smr[t] = hb_acc;
    __syncthreads();
    for (int st = 128; st > 0; st >>= 1) {
        if (t < st) smr[t] += smr[t + st];
        __syncthreads();
    }
    if (t == 0) atomicAdd(&hb[b], smr[0]);
}

// ====== online-softmax attention, pass 1: scores + partial contexts ==========
// grid (64 b, 4 l-chunks) = 256 CTAs (single wave at occ 2).
// 8 warps; warp owns 8 l's. enc read exactly once.
__global__ __launch_bounds__(256)
void attn_part(const float* __restrict__ q, const float* __restrict__ enc,
               const float* __restrict__ hb, float* __restrict__ scores,
               float* __restrict__ ctxp, float2* __restrict__ msp) {
    const int b = blockIdx.x, chunk = blockIdx.y;
    const int tid = threadIdx.x, wid = tid >> 5, lane = tid & 31;
    __shared__ float swap[8 * 1024];
    __shared__ float sm_m[8], sm_s[8];

    float4 qv[8];
    const float4* qp = (const float4*)(q + (size_t)b * HH);
#pragma unroll
    for (int rp = 0; rp < 8; rp++) qv[rp] = qp[lane + rp * 32];

    float4 acc[8];
#pragma unroll
    for (int rp = 0; rp < 8; rp++) acc[rp] = make_float4(0.f, 0.f, 0.f, 0.f);
    float m = -INFINITY, ssum = 0.f;
    const float hbv = hb[b];
    const int l0 = chunk * 64 + wid * 8;

    for (int li = 0; li < 8; li++) {
        const int l = l0 + li;
        const float4* ep = (const float4*)(enc + ((size_t)l * BB + b) * HH);
        float4 ev[8];
        float dot = 0.f;
#pragma unroll
        for (int rp = 0; rp < 8; rp++) {
            ev[rp] = ep[lane + rp * 32];
            dot += ev[rp].x * qv[rp].x + ev[rp].y * qv[rp].y
                 + ev[rp].z * qv[rp].z + ev[rp].w * qv[rp].w;
        }
#pragma unroll
        for (int o = 16; o > 0; o >>= 1) dot += __shfl_xor_sync(0xffffffffu, dot, o);
        float s_l = dot + hbv;
        if (lane == 0) scores[(size_t)b * LL + l] = s_l;
        float m_new = fmaxf(m, s_l);
        float scale = expf(m - m_new);
        float p = expf(s_l - m_new);
        ssum = ssum * scale + p;
#pragma unroll
        for (int rp = 0; rp < 8; rp++) {
            acc[rp].x = acc[rp].x * scale + p * ev[rp].x;
            acc[rp].y = acc[rp].y * scale + p * ev[rp].y;
            acc[rp].z = acc[rp].z * scale + p * ev[rp].z;
            acc[rp].w = acc[rp].w * scale + p * ev[rp].w;
        }
        m = m_new;
    }

    // CTA combine (8 warp partials -> 1)
    float4* wp = (float4*)(swap + wid * 1024);
#pragma unroll
    for (int rp = 0; rp < 8; rp++) wp[lane + rp * 32] = acc[rp];
    if (lane == 0) { sm_m[wid] = m; sm_s[wid] = ssum; }
    __syncthreads();

    float mc = sm_m[0];
#pragma unroll
    for (int w2 = 1; w2 < 8; w2++) mc = fmaxf(mc, sm_m[w2]);
    float scl[8];
    float sc_sum = 0.f;
#pragma unroll
    for (int w2 = 0; w2 < 8; w2++) {
        scl[w2] = expf(sm_m[w2] - mc);
        sc_sum += scl[w2] * sm_s[w2];
    }
    float4 cx = make_float4(0.f, 0.f, 0.f, 0.f);
#pragma unroll
    for (int w2 = 0; w2 < 8; w2++) {
        float4 v = ((float4*)(swap + w2 * 1024))[tid];
        cx.x += scl[w2] * v.x; cx.y += scl[w2] * v.y;
        cx.z += scl[w2] * v.z; cx.w += scl[w2] * v.w;
    }
    ((float4*)(ctxp + ((size_t)b * 4 + chunk) * HH))[tid] = cx;
    if (tid == 0) msp[b * 4 + chunk] = make_float2(mc, sc_sum);
}

// ====== online-softmax attention, pass 2: merge partials + outputs ===========
__global__ void attn_reduce(const float* __restrict__ scores,
                            const float* __restrict__ ctxp,
                            const float2* __restrict__ msp,
                            float* __restrict__ out_attn,
                            __half* __restrict__ cat_hi,
                            __half* __restrict__ cat_lo) {
    const int b = blockIdx.x, t = threadIdx.x;  // 256 threads
    float2 ms[4];
#pragma unroll
    for (int c = 0; c < 4; c++) ms[c] = msp[b * 4 + c];
    float M = ms[0].x;
#pragma unroll
    for (int c = 1; c < 4; c++) M = fmaxf(M, ms[c].x);
    float S = 0.f;
    float scl[4];
#pragma unroll
    for (int c = 0; c < 4; c++) {
        scl[c] = expf(ms[c].x - M);
        S += scl[c] * ms[c].y;
    }
    float invS = 1.f / S;

    float4 cx = make_float4(0.f, 0.f, 0.f, 0.f);
#pragma unroll
    for (int c = 0; c < 4; c++) {
        float4 v = ((const float4*)(ctxp + ((size_t)b * 4 + c) * HH))[t];
        cx.x += scl[c] * v.x; cx.y += scl[c] * v.y;
        cx.z += scl[c] * v.z; cx.w += scl[c] * v.w;
    }
    cx.x *= invS; cx.y *= invS; cx.z *= invS; cx.w *= invS;

    size_t o = (size_t)b * 2048 + 1024 + t * 4;
    float hx = __half2float(__float2half_rn(cx.x));
    float hy = __half2float(__float2half_rn(cx.y));
    float hz = __half2float(__float2half_rn(cx.z));
    float hw = __half2float(__float2half_rn(cx.w));
    *(uint2*)(cat_hi + o) = make_uint2(pack_h(cx.x, cx.y), pack_h(cx.z, cx.w));
    *(uint2*)(cat_lo + o) = make_uint2(pack_h(cx.x - hx, cx.y - hy),
                                       pack_h(cx.z - hz, cx.w - hw));

    float w = expf(scores[(size_t)b * LL + t] - M) * invS;
    out_attn[(size_t)b * LL + t] = w;
}

// ================= launch =====================================================
extern "C" void kernel_launch(void* const* d_in, const int* in_sizes, int n_in,
                              void* d_out, int out_size) {
    const int*   seq  = (const int*)d_in[0];
    const float* h0   = (const float*)d_in[1];
    const float* enc  = (const float*)d_in[2];
    const float* emb  = (const float*)d_in[3];
    const float* w_ih = (const float*)d_in[4];
    const float* w_hh = (const float*)d_in[5];
    const float* b_ih = (const float*)d_in[6];
    const float* b_hh = (const float*)d_in[7];
    const float* attw = (const float*)d_in[8];
    const float* attb = (const float*)d_in[9];
    const float* cw   = (const float*)d_in[10];
    const float* cb   = (const float*)d_in[11];
    const float* ow   = (const float*)d_in[12];
    const float* ob   = (const float*)d_in[13];

    float* out        = (float*)d_out;                  // [B, V]
    float* out_hidden = out + (size_t)BB * VV;          // [B, H]
    float* out_attn   = out_hidden + (size_t)BB * HH;   // [B, L]

    cudaFuncSetAttribute(hmma_gemm<3>,
                         cudaFuncAttributeMaxDynamicSharedMemorySize, SMEM_NP3);
    cudaFuncSetAttribute(hmma_gemm<1>,
                         cudaFuncAttributeMaxDynamicSharedMemorySize, SMEM_NP1);

    __half *xhi, *xlo, *hhi, *hlo, *chi, *cathi, *catlo;
    float *gi, *gh, *hb, *q, *sc, *cp, *ctxp;
    float2* msp;
    cudaGetSymbolAddress((void**)&xhi, g_xhi);
    cudaGetSymbolAddress((void**)&xlo, g_xlo);
    cudaGetSymbolAddress((void**)&hhi, g_hhi);
    cudaGetSymbolAddress((void**)&hlo, g_hlo);
    cudaGetSymbolAddress((void**)&chi, g_chi);
    cudaGetSymbolAddress((void**)&cathi, g_cat_hi);
    cudaGetSymbolAddress((void**)&catlo, g_cat_lo);
    cudaGetSymbolAddress((void**)&gi, g_gi);
    cudaGetSymbolAddress((void**)&gh, g_gh);
    cudaGetSymbolAddress((void**)&hb, g_hb);
    cudaGetSymbolAddress((void**)&q, g_q);
    cudaGetSymbolAddress((void**)&sc, g_scores);
    cudaGetSymbolAddress((void**)&cp, g_cp);
    cudaGetSymbolAddress((void**)&ctxp, g_ctxp);
    cudaGetSymbolAddress((void**)&msp, g_msp);

    // 1) fp16 hi/lo splits (emb gather + h0) + zero all atomic accumulators
    split_all<<<128, 256>>>(seq, emb, h0, xhi, xlo, hhi, hlo, q, cp, hb, gi, gh);

    // 2) GRU gate GEMMs (3-pass; split-K=8 -> 384 CTAs, atomic epilogue)
    hmma_gemm<3><<<dim3(24, 2, 8), 256, SMEM_NP3>>>(
        xhi, xlo, w_ih, gi, hhi, hlo, w_hh, gh,
        nullptr, H3, EE, H3, EE, 0, 0, 1);

    // 3) gates -> h_new (hidden output, cat hi/lo first half, hb via atomics)
    gru_combine_hb<<<dim3(BB, 4), 256>>>(gi, gh, b_ih, b_hh, h0, attb,
                                         cathi, catlo, out_hidden, hb);

    // 4) q = h_new @ attn_w (3-pass, transposed W, split-K=16, atomic epilogue)
    hmma_gemm<3><<<dim3(8, 1, 16), 256, SMEM_NP3>>>(
        cathi, catlo, attw, q, cathi, catlo, attw, q,
        nullptr, HH, HH, HH, 2048, HH, 1, 1);

    // 5) online-softmax attention: enc read once (256 CTAs = 1 wave) + merge
    attn_part<<<dim3(BB, 4), 256>>>(q, enc, hb, sc, ctxp, msp);
    attn_reduce<<<BB, 256>>>(sc, ctxp, msp, out_attn, cathi, catlo);

    // 6) concat GEMM (NP=1, split-K=16, atomic epilogue) -> tanh+fp16
    hmma_gemm<1><<<dim3(8, 1, 16), 256, SMEM_NP1>>>(
        cathi, cathi, cw, cp, cathi, cathi, cw, cp,
        nullptr, HH, 2048, HH, 2048, 0, 0, 1);
    reduce_tanh_split<<<(BB * HH) / 256, 256>>>(cp, cb, chi);

    // 7) big V-GEMM: single-pass fp16, occ 3 (393 CTAs -> single wave)
    hmma_gemm<1><<<dim3((VV + 127) / 128, 1, 1), 256, SMEM_NP1>>>(
        chi, chi, ow, out, chi, chi, ow, out,
        ob, VV, HH, VV, HH, 0, 0, 0);
}